// round 16
// baseline (speedup 1.0000x reference)
#include <cuda_runtime.h>
#include <cuda_fp16.h>
#include <math.h>
#include <stdint.h>

// Problem constants
#define Bc   4
#define Sc   2048
#define Dc   512
#define Hc   8
#define Dhc  64
#define Mrows (Bc*Sc)      // 8192
#define D3   (3*Dc)        // 1536
#define DffC (4*Dc)        // 2048

// ---- scratch (device globals; no cudaMalloc allowed) ----
__device__ __half g_fw[3145728];
#define FW_IN   0
#define FW_OUT  786432
#define FW_FF1  1048576
#define FW_FF2  2097152
__device__ __half g_a16  [(size_t)Mrows * Dc];
__device__ __half g_ff16 [(size_t)Mrows * DffC];
__device__ __half g_qkv16[(size_t)Mrows * D3];
__device__ float  g_x1   [(size_t)Mrows * Dc];

// ============================================================
// helpers
// ============================================================
__device__ __forceinline__ uint32_t smem_u32(const void* p) {
    uint32_t a;
    asm("{ .reg .u64 t; cvta.to.shared.u64 t, %1; cvt.u32.u64 %0, t; }" : "=r"(a) : "l"(p));
    return a;
}
__device__ __forceinline__ uint32_t sw128(uint32_t o) { return o ^ ((o >> 3) & 0x70); }

__device__ __forceinline__ void cp16(uint32_t dst, const void* src) {
    asm volatile("cp.async.cg.shared.global [%0], [%1], 16;" :: "r"(dst), "l"(src) : "memory");
}
#define CP_COMMIT() asm volatile("cp.async.commit_group;" ::: "memory")
#define CP_WAIT1()  asm volatile("cp.async.wait_group 1;" ::: "memory")
#define CP_WAIT2()  asm volatile("cp.async.wait_group 2;" ::: "memory")

__device__ __forceinline__ void ldm_x4(uint32_t* r, uint32_t addr) {
    asm volatile("ldmatrix.sync.aligned.m8n8.x4.shared.b16 {%0,%1,%2,%3}, [%4];"
                 : "=r"(r[0]), "=r"(r[1]), "=r"(r[2]), "=r"(r[3]) : "r"(addr));
}
__device__ __forceinline__ void mma_f16(float* c, const uint32_t* a, uint32_t b0, uint32_t b1) {
    asm volatile("mma.sync.aligned.m16n8k16.row.col.f32.f16.f16.f32 "
                 "{%0,%1,%2,%3}, {%4,%5,%6,%7}, {%8,%9}, {%0,%1,%2,%3};"
                 : "+f"(c[0]), "+f"(c[1]), "+f"(c[2]), "+f"(c[3])
                 : "r"(a[0]), "r"(a[1]), "r"(a[2]), "r"(a[3]), "r"(b0), "r"(b1));
}

// ============================================================
// Fused prologue: weight conversion (blocks 0..767, 8x ILP) and
// LN1 -> fp16(/32) (blocks 768..8959, one row each).
// ============================================================
__device__ __forceinline__ void wconv_one(int i,
    const float* __restrict__ in_w, const float* __restrict__ out_w,
    const float* __restrict__ w1, const float* __restrict__ w2,
    __half* __restrict__ hi) {
    float4 v;
    if      (i < 196608) v = ((const float4*)in_w)[i];
    else if (i < 262144) v = ((const float4*)out_w)[i - 196608];
    else if (i < 524288) v = ((const float4*)w1)[i - 262144];
    else                 v = ((const float4*)w2)[i - 524288];
    __half2 p0 = __floats2half2_rn(v.x * 32.0f, v.y * 32.0f);
    __half2 p1 = __floats2half2_rn(v.z * 32.0f, v.w * 32.0f);
    ((uint2*)hi)[i] = make_uint2(*reinterpret_cast<uint32_t*>(&p0),
                                 *reinterpret_cast<uint32_t*>(&p1));
}

__device__ __forceinline__ void ln_row(int row, const float* __restrict__ x,
                                       const float* __restrict__ g,
                                       const float* __restrict__ b,
                                       __half* __restrict__ h16, int t) {
    const float4* xr = (const float4*)(x + (size_t)row * Dc);
    float4 v = xr[t];
    float s  = v.x + v.y + v.z + v.w;
    float s2 = v.x*v.x + v.y*v.y + v.z*v.z + v.w*v.w;
    #pragma unroll
    for (int o = 16; o > 0; o >>= 1) {
        s  += __shfl_xor_sync(0xffffffffu, s,  o);
        s2 += __shfl_xor_sync(0xffffffffu, s2, o);
    }
    __shared__ float sh[8];
    int w = t >> 5;
    if ((t & 31) == 0) { sh[w*2] = s; sh[w*2+1] = s2; }
    __syncthreads();
    s  = sh[0] + sh[2] + sh[4] + sh[6];
    s2 = sh[1] + sh[3] + sh[5] + sh[7];
    float mu  = s * (1.0f / Dc);
    float var = s2 * (1.0f / Dc) - mu * mu;
    float rstd = rsqrtf(var + 1e-5f);
    float4 gv = ((const float4*)g)[t];
    float4 bv = ((const float4*)b)[t];
    float o0 = (v.x - mu) * rstd * gv.x + bv.x;
    float o1 = (v.y - mu) * rstd * gv.y + bv.y;
    float o2 = (v.z - mu) * rstd * gv.z + bv.z;
    float o3 = (v.w - mu) * rstd * gv.w + bv.w;
    __half2 p0 = __floats2half2_rn(o0 * 0.03125f, o1 * 0.03125f);
    __half2 p1 = __floats2half2_rn(o2 * 0.03125f, o3 * 0.03125f);
    size_t base = (size_t)row * Dc + t * 4;
    *(uint2*)(h16 + base) = make_uint2(*reinterpret_cast<uint32_t*>(&p0),
                                       *reinterpret_cast<uint32_t*>(&p1));
}

__global__ void prologue_kernel(const float* __restrict__ in_w, const float* __restrict__ out_w,
                                const float* __restrict__ w1, const float* __restrict__ w2,
                                __half* __restrict__ fw,
                                const float* __restrict__ x,
                                const float* __restrict__ ln1_g, const float* __restrict__ ln1_b,
                                __half* __restrict__ a16) {
    int blk = blockIdx.x;
    if (blk < 768) {
        int i = blk * 128 + threadIdx.x;
        #pragma unroll
        for (int t = 0; t < 8; t++)
            wconv_one(i + t * 98304, in_w, out_w, w1, w2, fw);
    } else {
        ln_row(blk - 768, x, ln1_g, ln1_b, a16, threadIdx.x);
    }
}

__global__ void ln_kernel(const float* __restrict__ x,
                          const float* __restrict__ g,
                          const float* __restrict__ b,
                          __half* __restrict__ h16) {
    ln_row(blockIdx.x, x, g, b, h16, threadIdx.x);
}

// ============================================================
// 128x128 GEMM (4 warps of 64x64), 3-stage, 2 CTAs/SM.
// EPI: 0=bias->fp16, 2=bias+GELU->fp16(/32)
// ============================================================
#define TB  16384
#define SSZ (2*TB)
#define SM_SZ (3*SSZ)        // 98304

template<int EPI>
__global__ __launch_bounds__(128, 2)
void gemm_mma(const __half* __restrict__ Ahi, const __half* __restrict__ Bhi,
              const float* __restrict__ bias,
              __half* __restrict__ C16,
              int M, int N, int K)
{
    extern __shared__ __align__(128) char smem[];
    uint32_t sb = smem_u32(smem);
    int tid = threadIdx.x;
    int lane = tid & 31, wid = tid >> 5;
    int bm = blockIdx.y * 128, bn = blockIdx.x * 128;
    int m0 = (wid & 1) * 64;
    int n0 = (wid >> 1) * 64;

    float acc[4][8][4];
    #pragma unroll
    for (int i = 0; i < 4; i++)
        #pragma unroll
        for (int j = 0; j < 8; j++)
            #pragma unroll
            for (int k = 0; k < 4; k++) acc[i][j][k] = 0.0f;

    auto load_stage = [&](int st, int k0) {
        uint32_t base = sb + st * SSZ;
        #pragma unroll
        for (int t = 0; t < 8; t++) {
            int line = tid + t * 128;
            int r  = line >> 3;
            int cc = line & 7;
            uint32_t d = sw128((uint32_t)(r * 128 + cc * 16));
            cp16(base + d,      Ahi + (size_t)(bm + r) * K + k0 + cc * 8);
            cp16(base + TB + d, Bhi + (size_t)(bn + r) * K + k0 + cc * 8);
        }
    };

    int nk = K >> 6;
    load_stage(0, 0);  CP_COMMIT();
    load_stage(1, 64); CP_COMMIT();

    int st = 0;
    for (int ch = 0; ch < nk; ch++) {
        CP_WAIT1();
        __syncthreads();
        if (ch + 2 < nk) {
            int st2 = st + 2; if (st2 >= 3) st2 -= 3;
            load_stage(st2, (ch + 2) * 64);
        }
        CP_COMMIT();

        uint32_t abase = sb + st * SSZ;
        uint32_t bbase = abase + TB;

        #pragma unroll
        for (int ks = 0; ks < 4; ks++) {
            int k0 = ks * 16;
            int frow = (lane & 7) + ((lane >> 3) & 1) * 8;
            int fcol = k0 + (lane >> 4) * 8;
            uint32_t ahi[4][4], bh[4][4];
            #pragma unroll
            for (int mi = 0; mi < 4; mi++) {
                uint32_t o = sw128((uint32_t)((m0 + mi*16 + frow) * 128 + fcol * 2));
                ldm_x4(ahi[mi], abase + o);
            }
            #pragma unroll
            for (int pr = 0; pr < 4; pr++) {
                uint32_t o = sw128((uint32_t)((n0 + pr*16 + frow) * 128 + fcol * 2));
                ldm_x4(bh[pr], bbase + o);
            }
            #pragma unroll
            for (int mi = 0; mi < 4; mi++)
                #pragma unroll
                for (int ni = 0; ni < 8; ni++) {
                    int pr = ni >> 1, sel = ni & 1;
                    mma_f16(acc[mi][ni], ahi[mi], bh[pr][sel], bh[pr][sel+2]);
                }
        }
        st++; if (st >= 3) st = 0;
    }

    int gr = lane >> 2, tq = lane & 3;
    #pragma unroll
    for (int mi = 0; mi < 4; mi++) {
        #pragma unroll
        for (int ni = 0; ni < 8; ni++) {
            int col = bn + n0 + ni*8 + tq*2;
            float b0 = bias[col], b1 = bias[col + 1];
            #pragma unroll
            for (int half = 0; half < 2; half++) {
                int row = bm + m0 + mi*16 + gr + half*8;
                float v0 = acc[mi][ni][half*2 + 0] + b0;
                float v1 = acc[mi][ni][half*2 + 1] + b1;
                size_t off = (size_t)row * N + col;
                if (EPI == 2) {
                    v0 = 0.5f * v0 * (1.0f + erff(v0 * 0.7071067811865475f));
                    v1 = 0.5f * v1 * (1.0f + erff(v1 * 0.7071067811865475f));
                    __half2 p = __floats2half2_rn(v0 * 0.03125f, v1 * 0.03125f);
                    *(uint32_t*)(C16 + off) = *reinterpret_cast<uint32_t*>(&p);
                } else {
                    __half2 p = __floats2half2_rn(v0, v1);
                    *(uint32_t*)(C16 + off) = *reinterpret_cast<uint32_t*>(&p);
                }
            }
        }
    }
}

// ============================================================
// 256x128 GEMM, 8 warps of 64x64 (256 thr) — measured best for K=512
// (out-proj). 4-stage, 1 CTA/SM, grid=128 = one balanced wave.
// Epilogue: bias + residual -> fp32.
// ============================================================
#define ATB 32768
#define BTB 16384
#define SSZL (ATB + BTB)     // 49152
#define SM_SZL (4*SSZL)      // 196608

__global__ __launch_bounds__(256, 1)
void gemm_mma_l8(const __half* __restrict__ Ahi, const __half* __restrict__ Bhi,
                 const float* __restrict__ bias, const float* __restrict__ res,
                 float* __restrict__ C,
                 int M, int N, int K)
{
    extern __shared__ __align__(128) char smem[];
    uint32_t sb = smem_u32(smem);
    int tid = threadIdx.x;
    int lane = tid & 31, wid = tid >> 5;
    int bm = blockIdx.y * 256, bn = blockIdx.x * 128;
    int m0 = (wid & 3) * 64;
    int n0 = (wid >> 2) * 64;

    float acc[4][8][4];
    #pragma unroll
    for (int i = 0; i < 4; i++)
        #pragma unroll
        for (int j = 0; j < 8; j++)
            #pragma unroll
            for (int k = 0; k < 4; k++) acc[i][j][k] = 0.0f;

    auto load_stage = [&](int st, int k0) {
        uint32_t base = sb + st * SSZL;
        #pragma unroll
        for (int t = 0; t < 8; t++) {
            int line = tid + t * 256;
            int r  = line >> 3;
            int cc = line & 7;
            uint32_t d = sw128((uint32_t)(r * 128 + cc * 16));
            cp16(base + d, Ahi + (size_t)(bm + r) * K + k0 + cc * 8);
        }
        #pragma unroll
        for (int t = 0; t < 4; t++) {
            int line = tid + t * 256;
            int r  = line >> 3;
            int cc = line & 7;
            uint32_t d = sw128((uint32_t)(r * 128 + cc * 16));
            cp16(base + ATB + d, Bhi + (size_t)(bn + r) * K + k0 + cc * 8);
        }
    };

    int nk = K >> 6;
    load_stage(0, 0);   CP_COMMIT();
    load_stage(1, 64);  CP_COMMIT();
    load_stage(2, 128); CP_COMMIT();

    int st = 0;
    for (int ch = 0; ch < nk; ch++) {
        CP_WAIT2();
        __syncthreads();
        if (ch + 3 < nk) {
            int st3 = st + 3; if (st3 >= 4) st3 -= 4;
            load_stage(st3, (ch + 3) * 64);
        }
        CP_COMMIT();

        uint32_t abase = sb + st * SSZL;
        uint32_t bbase = abase + ATB;

        #pragma unroll
        for (int ks = 0; ks < 4; ks++) {
            int k0 = ks * 16;
            int frow = (lane & 7) + ((lane >> 3) & 1) * 8;
            int fcol = k0 + (lane >> 4) * 8;
            uint32_t ahi[4][4], bh[4][4];
            #pragma unroll
            for (int mi = 0; mi < 4; mi++) {
                uint32_t o = sw128((uint32_t)((m0 + mi*16 + frow) * 128 + fcol * 2));
                ldm_x4(ahi[mi], abase + o);
            }
            #pragma unroll
            for (int pr = 0; pr < 4; pr++) {
                uint32_t o = sw128((uint32_t)((n0 + pr*16 + frow) * 128 + fcol * 2));
                ldm_x4(bh[pr], bbase + o);
            }
            #pragma unroll
            for (int mi = 0; mi < 4; mi++)
                #pragma unroll
                for (int ni = 0; ni < 8; ni++) {
                    int pr = ni >> 1, sel = ni & 1;
                    mma_f16(acc[mi][ni], ahi[mi], bh[pr][sel], bh[pr][sel+2]);
                }
        }
        st++; if (st >= 4) st = 0;
    }

    int gr = lane >> 2, tq = lane & 3;
    #pragma unroll
    for (int mi = 0; mi < 4; mi++) {
        #pragma unroll
        for (int ni = 0; ni < 8; ni++) {
            int col = bn + n0 + ni*8 + tq*2;
            float b0 = bias[col], b1 = bias[col + 1];
            #pragma unroll
            for (int half = 0; half < 2; half++) {
                int row = bm + m0 + mi*16 + gr + half*8;
                size_t off = (size_t)row * N + col;
                float2 r2 = *(const float2*)(res + off);
                *(float2*)(C + off) = make_float2(acc[mi][ni][half*2+0] + b0 + r2.x,
                                                  acc[mi][ni][half*2+1] + b1 + r2.y);
            }
        }
    }
}

// ============================================================
// 256x128 GEMM, 16 warps of 64x32 (512 thr) — measured best for K=2048
// (FF2). 4-stage, 1 CTA/SM, grid=128 = one balanced wave.
// Epilogue: bias + residual -> fp32.
// ============================================================
__global__ __launch_bounds__(512, 1)
void gemm_mma_l16(const __half* __restrict__ Ahi, const __half* __restrict__ Bhi,
                  const float* __restrict__ bias, const float* __restrict__ res,
                  float* __restrict__ C,
                  int M, int N, int K)
{
    extern __shared__ __align__(128) char smem[];
    uint32_t sb = smem_u32(smem);
    int tid = threadIdx.x;
    int lane = tid & 31, wid = tid >> 5;
    int bm = blockIdx.y * 256, bn = blockIdx.x * 128;
    int m0 = (wid & 3) * 64;
    int n0 = (wid >> 2) * 32;

    float acc[4][4][4];
    #pragma unroll
    for (int i = 0; i < 4; i++)
        #pragma unroll
        for (int j = 0; j < 4; j++)
            #pragma unroll
            for (int k = 0; k < 4; k++) acc[i][j][k] = 0.0f;

    auto load_stage = [&](int st, int k0) {
        uint32_t base = sb + st * SSZL;
        #pragma unroll
        for (int t = 0; t < 4; t++) {
            int line = tid + t * 512;
            int r  = line >> 3;
            int cc = line & 7;
            uint32_t d = sw128((uint32_t)(r * 128 + cc * 16));
            cp16(base + d, Ahi + (size_t)(bm + r) * K + k0 + cc * 8);
        }
        #pragma unroll
        for (int t = 0; t < 2; t++) {
            int line = tid + t * 512;
            int r  = line >> 3;
            int cc = line & 7;
            uint32_t d = sw128((uint32_t)(r * 128 + cc * 16));
            cp16(base + ATB + d, Bhi + (size_t)(bn + r) * K + k0 + cc * 8);
        }
    };

    int nk = K >> 6;
    load_stage(0, 0);   CP_COMMIT();
    load_stage(1, 64);  CP_COMMIT();
    load_stage(2, 128); CP_COMMIT();

    int st = 0;
    for (int ch = 0; ch < nk; ch++) {
        CP_WAIT2();
        __syncthreads();
        if (ch + 3 < nk) {
            int st3 = st + 3; if (st3 >= 4) st3 -= 4;
            load_stage(st3, (ch + 3) * 64);
        }
        CP_COMMIT();

        uint32_t abase = sb + st * SSZL;
        uint32_t bbase = abase + ATB;

        #pragma unroll
        for (int ks = 0; ks < 4; ks++) {
            int k0 = ks * 16;
            int frow = (lane & 7) + ((lane >> 3) & 1) * 8;
            int fcol = k0 + (lane >> 4) * 8;
            uint32_t ahi[4][4], bh[2][4];
            #pragma unroll
            for (int mi = 0; mi < 4; mi++) {
                uint32_t o = sw128((uint32_t)((m0 + mi*16 + frow) * 128 + fcol * 2));
                ldm_x4(ahi[mi], abase + o);
            }
            #pragma unroll
            for (int pr = 0; pr < 2; pr++) {
                uint32_t o = sw128((uint32_t)((n0 + pr*16 + frow) * 128 + fcol * 2));
                ldm_x4(bh[pr], bbase + o);
            }
            #pragma unroll
            for (int mi = 0; mi < 4; mi++)
                #pragma unroll
                for (int ni = 0; ni < 4; ni++) {
                    int pr = ni >> 1, sel = ni & 1;
                    mma_f16(acc[mi][ni], ahi[mi], bh[pr][sel], bh[pr][sel+2]);
                }
        }
        st++; if (st >= 4) st = 0;
    }

    int gr = lane >> 2, tq = lane & 3;
    #pragma unroll
    for (int mi = 0; mi < 4; mi++) {
        #pragma unroll
        for (int ni = 0; ni < 4; ni++) {
            int col = bn + n0 + ni*8 + tq*2;
            float b0 = bias[col], b1 = bias[col + 1];
            #pragma unroll
            for (int half = 0; half < 2; half++) {
                int row = bm + m0 + mi*16 + gr + half*8;
                size_t off = (size_t)row * N + col;
                float2 r2 = *(const float2*)(res + off);
                *(float2*)(C + off) = make_float2(acc[mi][ni][half*2+0] + b0 + r2.x,
                                                  acc[mi][ni][half*2+1] + b1 + r2.y);
            }
        }
    }
}

// ============================================================
// Local attention: 2 threads per query (measured-best config).
// ============================================================
__global__ __launch_bounds__(256)
void attn_tq2(const __half* __restrict__ qkv16, __half* __restrict__ ctx16) {
    __shared__ uint32_t Ks[136 * 33];
    __shared__ uint32_t Vs[136 * 33];
    int blk = blockIdx.x;
    int span = blk & 15;
    int bh = blk >> 4;
    int h = bh & (Hc - 1), b = bh >> 3;
    int s0 = span * 128;
    int rowbase = b * Sc;
    int tid = threadIdx.x;

    #pragma unroll
    for (int t = 0; t < 5; t++) {
        int i = tid + t * 256;
        if (i < 136 * 8) {
            int r = i >> 3, c = i & 7;
            int j = s0 - 4 + r;
            uint4 kv = make_uint4(0,0,0,0), vv = make_uint4(0,0,0,0);
            if (j >= 0 && j < Sc) {
                const uint4* kp = (const uint4*)(qkv16 + (size_t)(rowbase + j) * D3 + Dc + h * Dhc);
                const uint4* vp = (const uint4*)(qkv16 + (size_t)(rowbase + j) * D3 + 2*Dc + h * Dhc);
                kv = kp[c]; vv = vp[c];
            }
            int base = r * 33 + c * 4;
            Ks[base+0] = kv.x; Ks[base+1] = kv.y; Ks[base+2] = kv.z; Ks[base+3] = kv.w;
            Vs[base+0] = vv.x; Vs[base+1] = vv.y; Vs[base+2] = vv.z; Vs[base+3] = vv.w;
        }
    }
    __syncthreads();

    int q  = tid >> 1;
    int hf = tid & 1;
    int s  = s0 + q;

    const uint4* qp = (const uint4*)(qkv16 + (size_t)(rowbase + s) * D3 + h * Dhc);
    float2 qf[16];
    #pragma unroll
    for (int c = 0; c < 4; c++) {
        uint4 u = qp[hf*4 + c];
        uint32_t w4[4] = {u.x, u.y, u.z, u.w};
        #pragma unroll
        for (int k = 0; k < 4; k++)
            qf[c*4 + k] = __half22float2(*reinterpret_cast<__half2*>(&w4[k]));
    }

    float e[9];
    #pragma unroll
    for (int jj = 0; jj < 9; jj++) e[jj] = 0.0f;
    #pragma unroll
    for (int d = 0; d < 16; d++) {
        float2 q2 = qf[d];
        #pragma unroll
        for (int jj = 0; jj < 9; jj++) {
            uint32_t kw = Ks[(q + jj) * 33 + hf*16 + d];
            float2 k2 = __half22float2(*reinterpret_cast<__half2*>(&kw));
            e[jj] = fmaf(q2.x, k2.x, fmaf(q2.y, k2.y, e[jj]));
        }
    }
    #pragma unroll
    for (int jj = 0; jj < 9; jj++)
        e[jj] += __shfl_xor_sync(0xffffffffu, e[jj], 1);

    float mx = -INFINITY;
    #pragma unroll
    for (int jj = 0; jj < 9; jj++) {
        int j = s - 4 + jj;
        e[jj] = (j >= 0 && j < Sc) ? e[jj] * 0.125f : -INFINITY;
        mx = fmaxf(mx, e[jj]);
    }
    float sum = 0.0f;
    #pragma unroll
    for (int jj = 0; jj < 9; jj++) { e[jj] = __expf(e[jj] - mx); sum += e[jj]; }
    float inv = 1.0f / sum;
    #pragma unroll
    for (int jj = 0; jj < 9; jj++) e[jj] *= inv;

    float cx[32];
    #pragma unroll
    for (int d = 0; d < 32; d++) cx[d] = 0.0f;
    #pragma unroll
    for (int jj = 0; jj < 9; jj++) {
        float w = e[jj];
        int base = (q + jj) * 33 + hf*16;
        #pragma unroll
        for (int d = 0; d < 16; d++) {
            uint32_t vw = Vs[base + d];
            float2 v2 = __half22float2(*reinterpret_cast<__half2*>(&vw));
            cx[2*d]     = fmaf(w, v2.x, cx[2*d]);
            cx[2*d + 1] = fmaf(w, v2.y, cx[2*d + 1]);
        }
    }
    uint32_t ow[16];
    #pragma unroll
    for (int d = 0; d < 16; d++) {
        __half2 p2 = __floats2half2_rn(cx[2*d] * 0.03125f, cx[2*d + 1] * 0.03125f);
        ow[d] = *reinterpret_cast<uint32_t*>(&p2);
    }
    uint4* op = (uint4*)(ctx16 + (size_t)(rowbase + s) * Dc + h * Dhc);
    #pragma unroll
    for (int c = 0; c < 4; c++)
        op[hf*4 + c] = make_uint4(ow[c*4], ow[c*4+1], ow[c*4+2], ow[c*4+3]);
}

// ============================================================
extern "C" void kernel_launch(void* const* d_in, const int* in_sizes, int n_in,
                              void* d_out, int out_size) {
    const float* x     = (const float*)d_in[0];
    const float* in_w  = (const float*)d_in[1];
    const float* in_b  = (const float*)d_in[2];
    const float* out_w = (const float*)d_in[3];
    const float* out_b = (const float*)d_in[4];
    const float* ff_w1 = (const float*)d_in[5];
    const float* ff_b1 = (const float*)d_in[6];
    const float* ff_w2 = (const float*)d_in[7];
    const float* ff_b2 = (const float*)d_in[8];
    const float* ln1_g = (const float*)d_in[9];
    const float* ln1_b = (const float*)d_in[10];
    const float* ln2_g = (const float*)d_in[11];
    const float* ln2_b = (const float*)d_in[12];
    float* out = (float*)d_out;

    __half *fw, *a16, *ff16, *qkv16;
    float *x1;
    cudaGetSymbolAddress((void**)&fw,    g_fw);
    cudaGetSymbolAddress((void**)&a16,   g_a16);
    cudaGetSymbolAddress((void**)&ff16,  g_ff16);
    cudaGetSymbolAddress((void**)&qkv16, g_qkv16);
    cudaGetSymbolAddress((void**)&x1,    g_x1);

    cudaFuncSetAttribute(gemm_mma<0>,  cudaFuncAttributeMaxDynamicSharedMemorySize, SM_SZ);
    cudaFuncSetAttribute(gemm_mma<2>,  cudaFuncAttributeMaxDynamicSharedMemorySize, SM_SZ);
    cudaFuncSetAttribute(gemm_mma_l8,  cudaFuncAttributeMaxDynamicSharedMemorySize, SM_SZL);
    cudaFuncSetAttribute(gemm_mma_l16, cudaFuncAttributeMaxDynamicSharedMemorySize, SM_SZL);

    // 0) fused prologue: weight conversion + LN1
    prologue_kernel<<<768 + Mrows, 128>>>(in_w, out_w, ff_w1, ff_w2, fw,
                                          x, ln1_g, ln1_b, a16);
    // 2) qkv16 = fp16(a16 @ (32*in_w)^T + in_b)
    gemm_mma<0><<<dim3(D3/128, Mrows/128), 128, SM_SZ>>>(
        a16, fw + FW_IN, in_b, qkv16, Mrows, D3, Dc);
    // 3) a16 = fp16(attention(qkv16)/32)
    attn_tq2<<<16 * Bc * Hc, 256>>>(qkv16, a16);
    // 4) x1 = x + a16 @ (32*out_w)^T + out_b   (K=512: 8-warp variant)
    gemm_mma_l8<<<dim3(Dc/128, Mrows/256), 256, SM_SZL>>>(
        a16, fw + FW_OUT, out_b, x, x1, Mrows, Dc, Dc);
    // 5) a16 = fp16(LN2(x1)/32)
    ln_kernel<<<Mrows, 128>>>(x1, ln2_g, ln2_b, a16);
    // 6) ff16 = fp16(gelu(a16 @ (32*ff_w1)^T + ff_b1)/32)
    gemm_mma<2><<<dim3(DffC/128, Mrows/128), 128, SM_SZ>>>(
        a16, fw + FW_FF1, ff_b1, ff16, Mrows, DffC, Dc);
    // 7) out = x1 + ff16 @ (32*ff_w2)^T + ff_b2   (K=2048: 16-warp variant)
    gemm_mma_l16<<<dim3(Dc/128, Mrows/256), 512, SM_SZL>>>(
        ff16, fw + FW_FF2, ff_b2, x1, out, Mrows, Dc, DffC);
}

// round 17
// speedup vs baseline: 1.0071x; 1.0071x over previous
#include <cuda_runtime.h>
#include <cuda_fp16.h>
#include <math.h>
#include <stdint.h>

// Problem constants
#define Bc   4
#define Sc   2048
#define Dc   512
#define Hc   8
#define Dhc  64
#define Mrows (Bc*Sc)      // 8192
#define D3   (3*Dc)        // 1536
#define DffC (4*Dc)        // 2048

// ---- scratch (device globals; no cudaMalloc allowed) ----
__device__ __half g_fw[3145728];
#define FW_IN   0
#define FW_OUT  786432
#define FW_FF1  1048576
#define FW_FF2  2097152
__device__ __half g_a16  [(size_t)Mrows * Dc];
__device__ __half g_ff16 [(size_t)Mrows * DffC];
__device__ __half g_qkv16[(size_t)Mrows * D3];
__device__ __half g_x1h  [(size_t)Mrows * Dc];   // x1 in fp16 (traffic cut)

// ============================================================
// helpers
// ============================================================
__device__ __forceinline__ uint32_t smem_u32(const void* p) {
    uint32_t a;
    asm("{ .reg .u64 t; cvta.to.shared.u64 t, %1; cvt.u32.u64 %0, t; }" : "=r"(a) : "l"(p));
    return a;
}
__device__ __forceinline__ uint32_t sw128(uint32_t o) { return o ^ ((o >> 3) & 0x70); }

__device__ __forceinline__ void cp16(uint32_t dst, const void* src) {
    asm volatile("cp.async.cg.shared.global [%0], [%1], 16;" :: "r"(dst), "l"(src) : "memory");
}
#define CP_COMMIT() asm volatile("cp.async.commit_group;" ::: "memory")
#define CP_WAIT1()  asm volatile("cp.async.wait_group 1;" ::: "memory")
#define CP_WAIT2()  asm volatile("cp.async.wait_group 2;" ::: "memory")

__device__ __forceinline__ void ldm_x4(uint32_t* r, uint32_t addr) {
    asm volatile("ldmatrix.sync.aligned.m8n8.x4.shared.b16 {%0,%1,%2,%3}, [%4];"
                 : "=r"(r[0]), "=r"(r[1]), "=r"(r[2]), "=r"(r[3]) : "r"(addr));
}
__device__ __forceinline__ void mma_f16(float* c, const uint32_t* a, uint32_t b0, uint32_t b1) {
    asm volatile("mma.sync.aligned.m16n8k16.row.col.f32.f16.f16.f32 "
                 "{%0,%1,%2,%3}, {%4,%5,%6,%7}, {%8,%9}, {%0,%1,%2,%3};"
                 : "+f"(c[0]), "+f"(c[1]), "+f"(c[2]), "+f"(c[3])
                 : "r"(a[0]), "r"(a[1]), "r"(a[2]), "r"(a[3]), "r"(b0), "r"(b1));
}

// ============================================================
// Fused prologue: weight conversion (blocks 0..767, 8x ILP) and
// LN1 -> fp16(/32) (blocks 768..8959, one row each).
// ============================================================
__device__ __forceinline__ void wconv_one(int i,
    const float* __restrict__ in_w, const float* __restrict__ out_w,
    const float* __restrict__ w1, const float* __restrict__ w2,
    __half* __restrict__ hi) {
    float4 v;
    if      (i < 196608) v = ((const float4*)in_w)[i];
    else if (i < 262144) v = ((const float4*)out_w)[i - 196608];
    else if (i < 524288) v = ((const float4*)w1)[i - 262144];
    else                 v = ((const float4*)w2)[i - 524288];
    __half2 p0 = __floats2half2_rn(v.x * 32.0f, v.y * 32.0f);
    __half2 p1 = __floats2half2_rn(v.z * 32.0f, v.w * 32.0f);
    ((uint2*)hi)[i] = make_uint2(*reinterpret_cast<uint32_t*>(&p0),
                                 *reinterpret_cast<uint32_t*>(&p1));
}

__device__ __forceinline__ void ln_row(int row, const float* __restrict__ x,
                                       const float* __restrict__ g,
                                       const float* __restrict__ b,
                                       __half* __restrict__ h16, int t) {
    const float4* xr = (const float4*)(x + (size_t)row * Dc);
    float4 v = xr[t];
    float s  = v.x + v.y + v.z + v.w;
    float s2 = v.x*v.x + v.y*v.y + v.z*v.z + v.w*v.w;
    #pragma unroll
    for (int o = 16; o > 0; o >>= 1) {
        s  += __shfl_xor_sync(0xffffffffu, s,  o);
        s2 += __shfl_xor_sync(0xffffffffu, s2, o);
    }
    __shared__ float sh[8];
    int w = t >> 5;
    if ((t & 31) == 0) { sh[w*2] = s; sh[w*2+1] = s2; }
    __syncthreads();
    s  = sh[0] + sh[2] + sh[4] + sh[6];
    s2 = sh[1] + sh[3] + sh[5] + sh[7];
    float mu  = s * (1.0f / Dc);
    float var = s2 * (1.0f / Dc) - mu * mu;
    float rstd = rsqrtf(var + 1e-5f);
    float4 gv = ((const float4*)g)[t];
    float4 bv = ((const float4*)b)[t];
    float o0 = (v.x - mu) * rstd * gv.x + bv.x;
    float o1 = (v.y - mu) * rstd * gv.y + bv.y;
    float o2 = (v.z - mu) * rstd * gv.z + bv.z;
    float o3 = (v.w - mu) * rstd * gv.w + bv.w;
    __half2 p0 = __floats2half2_rn(o0 * 0.03125f, o1 * 0.03125f);
    __half2 p1 = __floats2half2_rn(o2 * 0.03125f, o3 * 0.03125f);
    size_t base = (size_t)row * Dc + t * 4;
    *(uint2*)(h16 + base) = make_uint2(*reinterpret_cast<uint32_t*>(&p0),
                                       *reinterpret_cast<uint32_t*>(&p1));
}

__global__ void prologue_kernel(const float* __restrict__ in_w, const float* __restrict__ out_w,
                                const float* __restrict__ w1, const float* __restrict__ w2,
                                __half* __restrict__ fw,
                                const float* __restrict__ x,
                                const float* __restrict__ ln1_g, const float* __restrict__ ln1_b,
                                __half* __restrict__ a16) {
    int blk = blockIdx.x;
    if (blk < 768) {
        int i = blk * 128 + threadIdx.x;
        #pragma unroll
        for (int t = 0; t < 8; t++)
            wconv_one(i + t * 98304, in_w, out_w, w1, w2, fw);
    } else {
        ln_row(blk - 768, x, ln1_g, ln1_b, a16, threadIdx.x);
    }
}

// LN with fp16 input (for LN2 over x1h)
__global__ void ln16_kernel(const __half* __restrict__ xh,
                            const float* __restrict__ g,
                            const float* __restrict__ b,
                            __half* __restrict__ h16) {
    int row = blockIdx.x;
    int t = threadIdx.x;                 // 0..127
    uint2 u = ((const uint2*)(xh + (size_t)row * Dc))[t];
    float2 f0 = __half22float2(*reinterpret_cast<__half2*>(&u.x));
    float2 f1 = __half22float2(*reinterpret_cast<__half2*>(&u.y));
    float vx = f0.x, vy = f0.y, vz = f1.x, vw = f1.y;
    float s  = vx + vy + vz + vw;
    float s2 = vx*vx + vy*vy + vz*vz + vw*vw;
    #pragma unroll
    for (int o = 16; o > 0; o >>= 1) {
        s  += __shfl_xor_sync(0xffffffffu, s,  o);
        s2 += __shfl_xor_sync(0xffffffffu, s2, o);
    }
    __shared__ float sh[8];
    int w = t >> 5;
    if ((t & 31) == 0) { sh[w*2] = s; sh[w*2+1] = s2; }
    __syncthreads();
    s  = sh[0] + sh[2] + sh[4] + sh[6];
    s2 = sh[1] + sh[3] + sh[5] + sh[7];
    float mu  = s * (1.0f / Dc);
    float var = s2 * (1.0f / Dc) - mu * mu;
    float rstd = rsqrtf(var + 1e-5f);
    float4 gv = ((const float4*)g)[t];
    float4 bv = ((const float4*)b)[t];
    float o0 = (vx - mu) * rstd * gv.x + bv.x;
    float o1 = (vy - mu) * rstd * gv.y + bv.y;
    float o2 = (vz - mu) * rstd * gv.z + bv.z;
    float o3 = (vw - mu) * rstd * gv.w + bv.w;
    __half2 p0 = __floats2half2_rn(o0 * 0.03125f, o1 * 0.03125f);
    __half2 p1 = __floats2half2_rn(o2 * 0.03125f, o3 * 0.03125f);
    size_t base = (size_t)row * Dc + t * 4;
    *(uint2*)(h16 + base) = make_uint2(*reinterpret_cast<uint32_t*>(&p0),
                                       *reinterpret_cast<uint32_t*>(&p1));
}

// ============================================================
// 128x128 GEMM (4 warps of 64x64), 3-stage, 2 CTAs/SM.
// EPI: 0=bias->fp16, 2=bias+GELU->fp16(/32)
// ============================================================
#define TB  16384
#define SSZ (2*TB)
#define SM_SZ (3*SSZ)        // 98304

template<int EPI>
__global__ __launch_bounds__(128, 2)
void gemm_mma(const __half* __restrict__ Ahi, const __half* __restrict__ Bhi,
              const float* __restrict__ bias,
              __half* __restrict__ C16,
              int M, int N, int K)
{
    extern __shared__ __align__(128) char smem[];
    uint32_t sb = smem_u32(smem);
    int tid = threadIdx.x;
    int lane = tid & 31, wid = tid >> 5;
    int bm = blockIdx.y * 128, bn = blockIdx.x * 128;
    int m0 = (wid & 1) * 64;
    int n0 = (wid >> 1) * 64;

    float acc[4][8][4];
    #pragma unroll
    for (int i = 0; i < 4; i++)
        #pragma unroll
        for (int j = 0; j < 8; j++)
            #pragma unroll
            for (int k = 0; k < 4; k++) acc[i][j][k] = 0.0f;

    auto load_stage = [&](int st, int k0) {
        uint32_t base = sb + st * SSZ;
        #pragma unroll
        for (int t = 0; t < 8; t++) {
            int line = tid + t * 128;
            int r  = line >> 3;
            int cc = line & 7;
            uint32_t d = sw128((uint32_t)(r * 128 + cc * 16));
            cp16(base + d,      Ahi + (size_t)(bm + r) * K + k0 + cc * 8);
            cp16(base + TB + d, Bhi + (size_t)(bn + r) * K + k0 + cc * 8);
        }
    };

    int nk = K >> 6;
    load_stage(0, 0);  CP_COMMIT();
    load_stage(1, 64); CP_COMMIT();

    int st = 0;
    for (int ch = 0; ch < nk; ch++) {
        CP_WAIT1();
        __syncthreads();
        if (ch + 2 < nk) {
            int st2 = st + 2; if (st2 >= 3) st2 -= 3;
            load_stage(st2, (ch + 2) * 64);
        }
        CP_COMMIT();

        uint32_t abase = sb + st * SSZ;
        uint32_t bbase = abase + TB;

        #pragma unroll
        for (int ks = 0; ks < 4; ks++) {
            int k0 = ks * 16;
            int frow = (lane & 7) + ((lane >> 3) & 1) * 8;
            int fcol = k0 + (lane >> 4) * 8;
            uint32_t ahi[4][4], bh[4][4];
            #pragma unroll
            for (int mi = 0; mi < 4; mi++) {
                uint32_t o = sw128((uint32_t)((m0 + mi*16 + frow) * 128 + fcol * 2));
                ldm_x4(ahi[mi], abase + o);
            }
            #pragma unroll
            for (int pr = 0; pr < 4; pr++) {
                uint32_t o = sw128((uint32_t)((n0 + pr*16 + frow) * 128 + fcol * 2));
                ldm_x4(bh[pr], bbase + o);
            }
            #pragma unroll
            for (int mi = 0; mi < 4; mi++)
                #pragma unroll
                for (int ni = 0; ni < 8; ni++) {
                    int pr = ni >> 1, sel = ni & 1;
                    mma_f16(acc[mi][ni], ahi[mi], bh[pr][sel], bh[pr][sel+2]);
                }
        }
        st++; if (st >= 3) st = 0;
    }

    int gr = lane >> 2, tq = lane & 3;
    #pragma unroll
    for (int mi = 0; mi < 4; mi++) {
        #pragma unroll
        for (int ni = 0; ni < 8; ni++) {
            int col = bn + n0 + ni*8 + tq*2;
            float b0 = bias[col], b1 = bias[col + 1];
            #pragma unroll
            for (int half = 0; half < 2; half++) {
                int row = bm + m0 + mi*16 + gr + half*8;
                float v0 = acc[mi][ni][half*2 + 0] + b0;
                float v1 = acc[mi][ni][half*2 + 1] + b1;
                size_t off = (size_t)row * N + col;
                if (EPI == 2) {
                    v0 = 0.5f * v0 * (1.0f + erff(v0 * 0.7071067811865475f));
                    v1 = 0.5f * v1 * (1.0f + erff(v1 * 0.7071067811865475f));
                    __half2 p = __floats2half2_rn(v0 * 0.03125f, v1 * 0.03125f);
                    *(uint32_t*)(C16 + off) = *reinterpret_cast<uint32_t*>(&p);
                } else {
                    __half2 p = __floats2half2_rn(v0, v1);
                    *(uint32_t*)(C16 + off) = *reinterpret_cast<uint32_t*>(&p);
                }
            }
        }
    }
}

// ============================================================
// 256x128 GEMM, 8 warps of 64x64 (K=512, out-proj): 4-stage, 1 CTA/SM,
// grid=128 = one wave. Epilogue: bias + fp32 residual -> fp16 x1.
// ============================================================
#define ATB 32768
#define BTB 16384
#define SSZL (ATB + BTB)     // 49152
#define SM_SZL (4*SSZL)      // 196608

__global__ __launch_bounds__(256, 1)
void gemm_mma_l8(const __half* __restrict__ Ahi, const __half* __restrict__ Bhi,
                 const float* __restrict__ bias, const float* __restrict__ res,
                 __half* __restrict__ C16,
                 int M, int N, int K)
{
    extern __shared__ __align__(128) char smem[];
    uint32_t sb = smem_u32(smem);
    int tid = threadIdx.x;
    int lane = tid & 31, wid = tid >> 5;
    int bm = blockIdx.y * 256, bn = blockIdx.x * 128;
    int m0 = (wid & 3) * 64;
    int n0 = (wid >> 2) * 64;

    float acc[4][8][4];
    #pragma unroll
    for (int i = 0; i < 4; i++)
        #pragma unroll
        for (int j = 0; j < 8; j++)
            #pragma unroll
            for (int k = 0; k < 4; k++) acc[i][j][k] = 0.0f;

    auto load_stage = [&](int st, int k0) {
        uint32_t base = sb + st * SSZL;
        #pragma unroll
        for (int t = 0; t < 8; t++) {
            int line = tid + t * 256;
            int r  = line >> 3;
            int cc = line & 7;
            uint32_t d = sw128((uint32_t)(r * 128 + cc * 16));
            cp16(base + d, Ahi + (size_t)(bm + r) * K + k0 + cc * 8);
        }
        #pragma unroll
        for (int t = 0; t < 4; t++) {
            int line = tid + t * 256;
            int r  = line >> 3;
            int cc = line & 7;
            uint32_t d = sw128((uint32_t)(r * 128 + cc * 16));
            cp16(base + ATB + d, Bhi + (size_t)(bn + r) * K + k0 + cc * 8);
        }
    };

    int nk = K >> 6;
    load_stage(0, 0);   CP_COMMIT();
    load_stage(1, 64);  CP_COMMIT();
    load_stage(2, 128); CP_COMMIT();

    int st = 0;
    for (int ch = 0; ch < nk; ch++) {
        CP_WAIT2();
        __syncthreads();
        if (ch + 3 < nk) {
            int st3 = st + 3; if (st3 >= 4) st3 -= 4;
            load_stage(st3, (ch + 3) * 64);
        }
        CP_COMMIT();

        uint32_t abase = sb + st * SSZL;
        uint32_t bbase = abase + ATB;

        #pragma unroll
        for (int ks = 0; ks < 4; ks++) {
            int k0 = ks * 16;
            int frow = (lane & 7) + ((lane >> 3) & 1) * 8;
            int fcol = k0 + (lane >> 4) * 8;
            uint32_t ahi[4][4], bh[4][4];
            #pragma unroll
            for (int mi = 0; mi < 4; mi++) {
                uint32_t o = sw128((uint32_t)((m0 + mi*16 + frow) * 128 + fcol * 2));
                ldm_x4(ahi[mi], abase + o);
            }
            #pragma unroll
            for (int pr = 0; pr < 4; pr++) {
                uint32_t o = sw128((uint32_t)((n0 + pr*16 + frow) * 128 + fcol * 2));
                ldm_x4(bh[pr], bbase + o);
            }
            #pragma unroll
            for (int mi = 0; mi < 4; mi++)
                #pragma unroll
                for (int ni = 0; ni < 8; ni++) {
                    int pr = ni >> 1, sel = ni & 1;
                    mma_f16(acc[mi][ni], ahi[mi], bh[pr][sel], bh[pr][sel+2]);
                }
        }
        st++; if (st >= 4) st = 0;
    }

    int gr = lane >> 2, tq = lane & 3;
    #pragma unroll
    for (int mi = 0; mi < 4; mi++) {
        #pragma unroll
        for (int ni = 0; ni < 8; ni++) {
            int col = bn + n0 + ni*8 + tq*2;
            float b0 = bias[col], b1 = bias[col + 1];
            #pragma unroll
            for (int half = 0; half < 2; half++) {
                int row = bm + m0 + mi*16 + gr + half*8;
                size_t off = (size_t)row * N + col;
                float2 r2 = *(const float2*)(res + off);
                __half2 p = __floats2half2_rn(acc[mi][ni][half*2+0] + b0 + r2.x,
                                              acc[mi][ni][half*2+1] + b1 + r2.y);
                *(uint32_t*)(C16 + off) = *reinterpret_cast<uint32_t*>(&p);
            }
        }
    }
}

// ============================================================
// 256x128 GEMM, 16 warps of 64x32 (K=2048, FF2): 4-stage, 1 CTA/SM,
// grid=128 = one wave. Epilogue: bias + fp16 residual -> fp32 out.
// ============================================================
__global__ __launch_bounds__(512, 1)
void gemm_mma_l16(const __half* __restrict__ Ahi, const __half* __restrict__ Bhi,
                  const float* __restrict__ bias, const __half* __restrict__ res16,
                  float* __restrict__ C,
                  int M, int N, int K)
{
    extern __shared__ __align__(128) char smem[];
    uint32_t sb = smem_u32(smem);
    int tid = threadIdx.x;
    int lane = tid & 31, wid = tid >> 5;
    int bm = blockIdx.y * 256, bn = blockIdx.x * 128;
    int m0 = (wid & 3) * 64;
    int n0 = (wid >> 2) * 32;

    float acc[4][4][4];
    #pragma unroll
    for (int i = 0; i < 4; i++)
        #pragma unroll
        for (int j = 0; j < 4; j++)
            #pragma unroll
            for (int k = 0; k < 4; k++) acc[i][j][k] = 0.0f;

    auto load_stage = [&](int st, int k0) {
        uint32_t base = sb + st * SSZL;
        #pragma unroll
        for (int t = 0; t < 4; t++) {
            int line = tid + t * 512;
            int r  = line >> 3;
            int cc = line & 7;
            uint32_t d = sw128((uint32_t)(r * 128 + cc * 16));
            cp16(base + d, Ahi + (size_t)(bm + r) * K + k0 + cc * 8);
        }
        #pragma unroll
        for (int t = 0; t < 2; t++) {
            int line = tid + t * 512;
            int r  = line >> 3;
            int cc = line & 7;
            uint32_t d = sw128((uint32_t)(r * 128 + cc * 16));
            cp16(base + ATB + d, Bhi + (size_t)(bn + r) * K + k0 + cc * 8);
        }
    };

    int nk = K >> 6;
    load_stage(0, 0);   CP_COMMIT();
    load_stage(1, 64);  CP_COMMIT();
    load_stage(2, 128); CP_COMMIT();

    int st = 0;
    for (int ch = 0; ch < nk; ch++) {
        CP_WAIT2();
        __syncthreads();
        if (ch + 3 < nk) {
            int st3 = st + 3; if (st3 >= 4) st3 -= 4;
            load_stage(st3, (ch + 3) * 64);
        }
        CP_COMMIT();

        uint32_t abase = sb + st * SSZL;
        uint32_t bbase = abase + ATB;

        #pragma unroll
        for (int ks = 0; ks < 4; ks++) {
            int k0 = ks * 16;
            int frow = (lane & 7) + ((lane >> 3) & 1) * 8;
            int fcol = k0 + (lane >> 4) * 8;
            uint32_t ahi[4][4], bh[2][4];
            #pragma unroll
            for (int mi = 0; mi < 4; mi++) {
                uint32_t o = sw128((uint32_t)((m0 + mi*16 + frow) * 128 + fcol * 2));
                ldm_x4(ahi[mi], abase + o);
            }
            #pragma unroll
            for (int pr = 0; pr < 2; pr++) {
                uint32_t o = sw128((uint32_t)((n0 + pr*16 + frow) * 128 + fcol * 2));
                ldm_x4(bh[pr], bbase + o);
            }
            #pragma unroll
            for (int mi = 0; mi < 4; mi++)
                #pragma unroll
                for (int ni = 0; ni < 4; ni++) {
                    int pr = ni >> 1, sel = ni & 1;
                    mma_f16(acc[mi][ni], ahi[mi], bh[pr][sel], bh[pr][sel+2]);
                }
        }
        st++; if (st >= 4) st = 0;
    }

    int gr = lane >> 2, tq = lane & 3;
    #pragma unroll
    for (int mi = 0; mi < 4; mi++) {
        #pragma unroll
        for (int ni = 0; ni < 4; ni++) {
            int col = bn + n0 + ni*8 + tq*2;
            float b0 = bias[col], b1 = bias[col + 1];
            #pragma unroll
            for (int half = 0; half < 2; half++) {
                int row = bm + m0 + mi*16 + gr + half*8;
                size_t off = (size_t)row * N + col;
                uint32_t rw = *(const uint32_t*)(res16 + off);
                float2 r2 = __half22float2(*reinterpret_cast<__half2*>(&rw));
                *(float2*)(C + off) = make_float2(acc[mi][ni][half*2+0] + b0 + r2.x,
                                                  acc[mi][ni][half*2+1] + b1 + r2.y);
            }
        }
    }
}

// ============================================================
// Local attention: 2 threads per query (measured-best config).
// ============================================================
__global__ __launch_bounds__(256)
void attn_tq2(const __half* __restrict__ qkv16, __half* __restrict__ ctx16) {
    __shared__ uint32_t Ks[136 * 33];
    __shared__ uint32_t Vs[136 * 33];
    int blk = blockIdx.x;
    int span = blk & 15;
    int bh = blk >> 4;
    int h = bh & (Hc - 1), b = bh >> 3;
    int s0 = span * 128;
    int rowbase = b * Sc;
    int tid = threadIdx.x;

    #pragma unroll
    for (int t = 0; t < 5; t++) {
        int i = tid + t * 256;
        if (i < 136 * 8) {
            int r = i >> 3, c = i & 7;
            int j = s0 - 4 + r;
            uint4 kv = make_uint4(0,0,0,0), vv = make_uint4(0,0,0,0);
            if (j >= 0 && j < Sc) {
                const uint4* kp = (const uint4*)(qkv16 + (size_t)(rowbase + j) * D3 + Dc + h * Dhc);
                const uint4* vp = (const uint4*)(qkv16 + (size_t)(rowbase + j) * D3 + 2*Dc + h * Dhc);
                kv = kp[c]; vv = vp[c];
            }
            int base = r * 33 + c * 4;
            Ks[base+0] = kv.x; Ks[base+1] = kv.y; Ks[base+2] = kv.z; Ks[base+3] = kv.w;
            Vs[base+0] = vv.x; Vs[base+1] = vv.y; Vs[base+2] = vv.z; Vs[base+3] = vv.w;
        }
    }
    __syncthreads();

    int q  = tid >> 1;
    int hf = tid & 1;
    int s  = s0 + q;

    const uint4* qp = (const uint4*)(qkv16 + (size_t)(rowbase + s) * D3 + h * Dhc);
    float2 qf[16];
    #pragma unroll
    for (int c = 0; c < 4; c++) {
        uint4 u = qp[hf*4 + c];
        uint32_t w4[4] = {u.x, u.y, u.z, u.w};
        #pragma unroll
        for (int k = 0; k < 4; k++)
            qf[c*4 + k] = __half22float2(*reinterpret_cast<__half2*>(&w4[k]));
    }

    float e[9];
    #pragma unroll
    for (int jj = 0; jj < 9; jj++) e[jj] = 0.0f;
    #pragma unroll
    for (int d = 0; d < 16; d++) {
        float2 q2 = qf[d];
        #pragma unroll
        for (int jj = 0; jj < 9; jj++) {
            uint32_t kw = Ks[(q + jj) * 33 + hf*16 + d];
            float2 k2 = __half22float2(*reinterpret_cast<__half2*>(&kw));
            e[jj] = fmaf(q2.x, k2.x, fmaf(q2.y, k2.y, e[jj]));
        }
    }
    #pragma unroll
    for (int jj = 0; jj < 9; jj++)
        e[jj] += __shfl_xor_sync(0xffffffffu, e[jj], 1);

    float mx = -INFINITY;
    #pragma unroll
    for (int jj = 0; jj < 9; jj++) {
        int j = s - 4 + jj;
        e[jj] = (j >= 0 && j < Sc) ? e[jj] * 0.125f : -INFINITY;
        mx = fmaxf(mx, e[jj]);
    }
    float sum = 0.0f;
    #pragma unroll
    for (int jj = 0; jj < 9; jj++) { e[jj] = __expf(e[jj] - mx); sum += e[jj]; }
    float inv = 1.0f / sum;
    #pragma unroll
    for (int jj = 0; jj < 9; jj++) e[jj] *= inv;

    float cx[32];
    #pragma unroll
    for (int d = 0; d < 32; d++) cx[d] = 0.0f;
    #pragma unroll
    for (int jj = 0; jj < 9; jj++) {
        float w = e[jj];
        int base = (q + jj) * 33 + hf*16;
        #pragma unroll
        for (int d = 0; d < 16; d++) {
            uint32_t vw = Vs[base + d];
            float2 v2 = __half22float2(*reinterpret_cast<__half2*>(&vw));
            cx[2*d]     = fmaf(w, v2.x, cx[2*d]);
            cx[2*d + 1] = fmaf(w, v2.y, cx[2*d + 1]);
        }
    }
    uint32_t ow[16];
    #pragma unroll
    for (int d = 0; d < 16; d++) {
        __half2 p2 = __floats2half2_rn(cx[2*d] * 0.03125f, cx[2*d + 1] * 0.03125f);
        ow[d] = *reinterpret_cast<uint32_t*>(&p2);
    }
    uint4* op = (uint4*)(ctx16 + (size_t)(rowbase + s) * Dc + h * Dhc);
    #pragma unroll
    for (int c = 0; c < 4; c++)
        op[hf*4 + c] = make_uint4(ow[c*4], ow[c*4+1], ow[c*4+2], ow[c*4+3]);
}

// ============================================================
extern "C" void kernel_launch(void* const* d_in, const int* in_sizes, int n_in,
                              void* d_out, int out_size) {
    const float* x     = (const float*)d_in[0];
    const float* in_w  = (const float*)d_in[1];
    const float* in_b  = (const float*)d_in[2];
    const float* out_w = (const float*)d_in[3];
    const float* out_b = (const float*)d_in[4];
    const float* ff_w1 = (const float*)d_in[5];
    const float* ff_b1 = (const float*)d_in[6];
    const float* ff_w2 = (const float*)d_in[7];
    const float* ff_b2 = (const float*)d_in[8];
    const float* ln1_g = (const float*)d_in[9];
    const float* ln1_b = (const float*)d_in[10];
    const float* ln2_g = (const float*)d_in[11];
    const float* ln2_b = (const float*)d_in[12];
    float* out = (float*)d_out;

    __half *fw, *a16, *ff16, *qkv16, *x1h;
    cudaGetSymbolAddress((void**)&fw,    g_fw);
    cudaGetSymbolAddress((void**)&a16,   g_a16);
    cudaGetSymbolAddress((void**)&ff16,  g_ff16);
    cudaGetSymbolAddress((void**)&qkv16, g_qkv16);
    cudaGetSymbolAddress((void**)&x1h,   g_x1h);

    cudaFuncSetAttribute(gemm_mma<0>,  cudaFuncAttributeMaxDynamicSharedMemorySize, SM_SZ);
    cudaFuncSetAttribute(gemm_mma<2>,  cudaFuncAttributeMaxDynamicSharedMemorySize, SM_SZ);
    cudaFuncSetAttribute(gemm_mma_l8,  cudaFuncAttributeMaxDynamicSharedMemorySize, SM_SZL);
    cudaFuncSetAttribute(gemm_mma_l16, cudaFuncAttributeMaxDynamicSharedMemorySize, SM_SZL);

    // 0) fused prologue: weight conversion + LN1
    prologue_kernel<<<768 + Mrows, 128>>>(in_w, out_w, ff_w1, ff_w2, fw,
                                          x, ln1_g, ln1_b, a16);
    // 2) qkv16 = fp16(a16 @ (32*in_w)^T + in_b)
    gemm_mma<0><<<dim3(D3/128, Mrows/128), 128, SM_SZ>>>(
        a16, fw + FW_IN, in_b, qkv16, Mrows, D3, Dc);
    // 3) a16 = fp16(attention(qkv16)/32)
    attn_tq2<<<16 * Bc * Hc, 256>>>(qkv16, a16);
    // 4) x1h = fp16(x + a16 @ (32*out_w)^T + out_b)   (K=512: 8-warp)
    gemm_mma_l8<<<dim3(Dc/128, Mrows/256), 256, SM_SZL>>>(
        a16, fw + FW_OUT, out_b, x, x1h, Mrows, Dc, Dc);
    // 5) a16 = fp16(LN2(x1h)/32)
    ln16_kernel<<<Mrows, 128>>>(x1h, ln2_g, ln2_b, a16);
    // 6) ff16 = fp16(gelu(a16 @ (32*ff_w1)^T + ff_b1)/32)
    gemm_mma<2><<<dim3(DffC/128, Mrows/128), 128, SM_SZ>>>(
        a16, fw + FW_FF1, ff_b1, ff16, Mrows, DffC, Dc);
    // 7) out = x1h + ff16 @ (32*ff_w2)^T + ff_b2   (K=2048: 16-warp)
    gemm_mma_l16<<<dim3(Dc/128, Mrows/256), 512, SM_SZL>>>(
        ff16, fw + FW_FF2, ff_b2, x1h, out, Mrows, Dc, DffC);
}